// round 10
// baseline (speedup 1.0000x reference)
#include <cuda_runtime.h>
#include <math.h>

// Problem constants
constexpr int B_  = 4;
constexpr int C_  = 512;
constexpr int IC_ = 256;
constexpr int H_  = 64;
constexpr int N_  = 4096;   // H*W
constexpr int OT_ = 1024;   // q(256) + k(256) + v(512) output channels

// Static scratch (allocation-free rule: __device__ globals)
__device__ float g_W[OT_ * C_];          // packed projection weights [1024, 512]
__device__ float g_bias[OT_];
__device__ float g_QKV[B_][OT_][N_];     // 67 MB: rows 0-255 = q, 256-511 = k, 512-1023 = v
__device__ float g_sqQ[B_][N_];
__device__ float g_sqK[B_][N_];
__device__ float g_Rpart[B_][N_][32];    // deterministic partial row sums of E
__device__ float g_invR[B_][N_];
__device__ float g_E[B_][N_][N_];        // 268 MB: exp(-D)

// ---------------------------------------------------------------------------
// Pack qw/kw/vw into one [1024, 512] weight matrix + bias vector
// ---------------------------------------------------------------------------
__global__ void pack_kernel(const float* __restrict__ qw, const float* __restrict__ qb,
                            const float* __restrict__ kw, const float* __restrict__ kb,
                            const float* __restrict__ vw, const float* __restrict__ vb) {
    int idx = blockIdx.x * 256 + threadIdx.x;
    if (idx < OT_ * C_) {
        int o = idx / C_, c = idx % C_;
        float v;
        if (o < IC_)          v = qw[o * C_ + c];
        else if (o < 2 * IC_) v = kw[(o - IC_) * C_ + c];
        else                  v = vw[(o - 2 * IC_) * C_ + c];
        g_W[idx] = v;
    }
    if (idx < OT_) {
        float bv;
        if (idx < IC_)          bv = qb[idx];
        else if (idx < 2 * IC_) bv = kb[idx - IC_];
        else                    bv = vb[idx - 2 * IC_];
        g_bias[idx] = bv;
    }
}

// ---------------------------------------------------------------------------
// Generic 128x128x16 tiled GEMM, 256 threads, 8x8 microtile.
// MODE 1: QKV = relu(W @ F + bias)             A=g_W [M,K] rm, B=features [K,N]
// MODE 2: E = exp(2*(Q^T K) - sqQ - sqK), Rpart A=Q [K,M] km, B=K [K,N]
// MODE 3: out = (V*invR) @ E + features        A=V [M,K] rm (scaled), B=E [K,N]
// ---------------------------------------------------------------------------
template <int MODE>
__global__ __launch_bounds__(256)
void gemm_kernel(const float* __restrict__ feat, float* __restrict__ outp) {
    constexpr int BM = 128, BN = 128, BK = 16;
    constexpr int KT  = (MODE == 1) ? C_ : (MODE == 2 ? IC_ : N_);
    constexpr int LDA = (MODE == 1) ? C_ : N_;

    __shared__ float As[BK][BM + 4];
    __shared__ float Bs[BK][BN + 4];

    const int b  = blockIdx.z;
    const int m0 = blockIdx.y * BM;
    const int n0 = blockIdx.x * BN;
    const int tid = threadIdx.x;
    const int tx = tid & 15;      // 0..15 -> output cols
    const int ty = tid >> 4;      // 0..15 -> output rows

    const float* Ap;
    const float* Bp;
    if constexpr (MODE == 1) {
        Ap = g_W;
        Bp = feat + (long)b * C_ * N_;
    } else if constexpr (MODE == 2) {
        Ap = &g_QKV[b][0][0];          // Q, [IC, N] (K-major)
        Bp = &g_QKV[b][IC_][0];        // K, [IC, N]
    } else {
        Ap = &g_QKV[b][2 * IC_][0];    // V, [C, N] row-major
        Bp = &g_E[b][0][0];            // E, [N, N]
    }

    float acc[8][8];
#pragma unroll
    for (int i = 0; i < 8; i++)
#pragma unroll
        for (int j = 0; j < 8; j++) acc[i][j] = 0.f;

    for (int k0 = 0; k0 < KT; k0 += BK) {
        // ---- load A tile ----
        if constexpr (MODE == 2) {
            // A stored [K, Mtot]: rows k, coalesced along m. No transpose needed.
#pragma unroll
            for (int i = 0; i < 2; i++) {
                int id = tid + i * 256;          // 0..511 float4s
                int kk = id >> 5;                // 0..15
                int mc = id & 31;                // 0..31
                float4 v = *(const float4*)&Ap[(long)(k0 + kk) * N_ + m0 + mc * 4];
                *(float4*)&As[kk][mc * 4] = v;
            }
        } else {
            // A row-major [Mtot, K]: load along k, transpose into As[k][m]
#pragma unroll
            for (int i = 0; i < 2; i++) {
                int id  = tid + i * 256;
                int row = id >> 2;               // 0..127
                int kc  = id & 3;                // 0..3 (float4 within k-tile)
                float4 v = *(const float4*)&Ap[(long)(m0 + row) * LDA + k0 + kc * 4];
                if constexpr (MODE == 3) {
                    float4 iv = *(const float4*)&g_invR[b][k0 + kc * 4];
                    v.x *= iv.x; v.y *= iv.y; v.z *= iv.z; v.w *= iv.w;
                }
                As[kc * 4 + 0][row] = v.x;
                As[kc * 4 + 1][row] = v.y;
                As[kc * 4 + 2][row] = v.z;
                As[kc * 4 + 3][row] = v.w;
            }
        }
        // ---- load B tile [K, N] ----
#pragma unroll
        for (int i = 0; i < 2; i++) {
            int id = tid + i * 256;
            int kk = id >> 5;
            int nc = id & 31;
            float4 v = *(const float4*)&Bp[(long)(k0 + kk) * N_ + n0 + nc * 4];
            *(float4*)&Bs[kk][nc * 4] = v;
        }
        __syncthreads();

#pragma unroll
        for (int kk = 0; kk < BK; kk++) {
            float a[8], bv[8];
            *(float4*)&a[0]  = *(const float4*)&As[kk][ty * 4];
            *(float4*)&a[4]  = *(const float4*)&As[kk][64 + ty * 4];
            *(float4*)&bv[0] = *(const float4*)&Bs[kk][tx * 4];
            *(float4*)&bv[4] = *(const float4*)&Bs[kk][64 + tx * 4];
#pragma unroll
            for (int i = 0; i < 8; i++)
#pragma unroll
                for (int j = 0; j < 8; j++) acc[i][j] += a[i] * bv[j];
        }
        __syncthreads();
    }

    // ---- epilogues ----
    const int c0 = n0 + tx * 4;
    const int c1 = c0 + 64;

    if constexpr (MODE == 1) {
#pragma unroll
        for (int i = 0; i < 8; i++) {
            int row = m0 + ((i < 4) ? (ty * 4 + i) : (64 + ty * 4 + i - 4));
            float bias = g_bias[row];
            float4 r0, r1;
            r0.x = fmaxf(acc[i][0] + bias, 0.f);
            r0.y = fmaxf(acc[i][1] + bias, 0.f);
            r0.z = fmaxf(acc[i][2] + bias, 0.f);
            r0.w = fmaxf(acc[i][3] + bias, 0.f);
            r1.x = fmaxf(acc[i][4] + bias, 0.f);
            r1.y = fmaxf(acc[i][5] + bias, 0.f);
            r1.z = fmaxf(acc[i][6] + bias, 0.f);
            r1.w = fmaxf(acc[i][7] + bias, 0.f);
            *(float4*)&g_QKV[b][row][c0] = r0;
            *(float4*)&g_QKV[b][row][c1] = r1;
        }
    } else if constexpr (MODE == 2) {
        float4 sk0 = *(const float4*)&g_sqK[b][c0];
        float4 sk1 = *(const float4*)&g_sqK[b][c1];
#pragma unroll
        for (int i = 0; i < 8; i++) {
            int row = m0 + ((i < 4) ? (ty * 4 + i) : (64 + ty * 4 + i - 4));
            float sq = g_sqQ[b][row];
            float4 e0, e1;
            e0.x = __expf(2.f * acc[i][0] - sq - sk0.x);
            e0.y = __expf(2.f * acc[i][1] - sq - sk0.y);
            e0.z = __expf(2.f * acc[i][2] - sq - sk0.z);
            e0.w = __expf(2.f * acc[i][3] - sq - sk0.w);
            e1.x = __expf(2.f * acc[i][4] - sq - sk1.x);
            e1.y = __expf(2.f * acc[i][5] - sq - sk1.y);
            e1.z = __expf(2.f * acc[i][6] - sq - sk1.z);
            e1.w = __expf(2.f * acc[i][7] - sq - sk1.w);
            *(float4*)&g_E[b][row][c0] = e0;
            *(float4*)&g_E[b][row][c1] = e1;
            // deterministic partial row sum over this block's 128 columns:
            // per-thread 8 cols, then fixed-order shfl tree across 16 tx lanes
            float s = e0.x + e0.y + e0.z + e0.w + e1.x + e1.y + e1.z + e1.w;
            s += __shfl_xor_sync(0xffffffffu, s, 1);
            s += __shfl_xor_sync(0xffffffffu, s, 2);
            s += __shfl_xor_sync(0xffffffffu, s, 4);
            s += __shfl_xor_sync(0xffffffffu, s, 8);
            if (tx == 0) g_Rpart[b][row][blockIdx.x] = s;
        }
    } else {
        const float* fbase = feat + (long)b * C_ * N_;
        float* obase = outp + (long)b * C_ * N_;
#pragma unroll
        for (int i = 0; i < 8; i++) {
            int row = m0 + ((i < 4) ? (ty * 4 + i) : (64 + ty * 4 + i - 4));
            float4 f0 = *(const float4*)&fbase[(long)row * N_ + c0];
            float4 f1 = *(const float4*)&fbase[(long)row * N_ + c1];
            float4 r0, r1;
            r0.x = acc[i][0] + f0.x; r0.y = acc[i][1] + f0.y;
            r0.z = acc[i][2] + f0.z; r0.w = acc[i][3] + f0.w;
            r1.x = acc[i][4] + f1.x; r1.y = acc[i][5] + f1.y;
            r1.z = acc[i][6] + f1.z; r1.w = acc[i][7] + f1.w;
            *(float4*)&obase[(long)row * N_ + c0] = r0;
            *(float4*)&obase[(long)row * N_ + c1] = r1;
        }
    }
}

// ---------------------------------------------------------------------------
// Add coordinate-conv cc to q and k, compute squared norms
// ---------------------------------------------------------------------------
__global__ void prep_kernel(const float* __restrict__ cw, const float* __restrict__ cb) {
    int idx = blockIdx.x * 256 + threadIdx.x;   // b*N + n
    int b = idx >> 12;
    int n = idx & (N_ - 1);
    int i = n >> 6, j = n & 63;
    float x = -1.f + 2.f * j / 63.f;   // channel 0 varies along w
    float y = -1.f + 2.f * i / 63.f;   // channel 1 varies along h
    float sq_q = 0.f, sq_k = 0.f;
    for (int ic = 0; ic < IC_; ic++) {
        float cc = fmaxf(cw[2 * ic] * x + cw[2 * ic + 1] * y + cb[ic], 0.f);
        float q = g_QKV[b][ic][n] + cc;
        float k = g_QKV[b][IC_ + ic][n] + cc;
        g_QKV[b][ic][n] = q;
        g_QKV[b][IC_ + ic][n] = k;
        sq_q += q * q;
        sq_k += k * k;
    }
    g_sqQ[b][n] = sq_q;
    g_sqK[b][n] = sq_k;
}

// ---------------------------------------------------------------------------
// Reduce the 32 deterministic partials -> invR = 1/(rowsum + 1e-14)
// ---------------------------------------------------------------------------
__global__ void rred_kernel() {
    int idx = blockIdx.x * 256 + threadIdx.x;   // b*N + n
    int b = idx >> 12;
    int n = idx & (N_ - 1);
    float s = 0.f;
#pragma unroll
    for (int p = 0; p < 32; p++) s += g_Rpart[b][n][p];
    g_invR[b][n] = 1.f / (s + 1e-14f);
}

// ---------------------------------------------------------------------------
extern "C" void kernel_launch(void* const* d_in, const int* in_sizes, int n_in,
                              void* d_out, int out_size) {
    const float* features = (const float*)d_in[0];
    const float* qw = (const float*)d_in[1];
    const float* qb = (const float*)d_in[2];
    const float* kw = (const float*)d_in[3];
    const float* kb = (const float*)d_in[4];
    const float* vw = (const float*)d_in[5];
    const float* vb = (const float*)d_in[6];
    const float* cw = (const float*)d_in[7];
    const float* cb = (const float*)d_in[8];
    float* out = (float*)d_out;

    pack_kernel<<<(OT_ * C_ + 255) / 256, 256>>>(qw, qb, kw, kb, vw, vb);

    dim3 g1(N_ / 128, OT_ / 128, B_);     // (32, 8, 4)
    gemm_kernel<1><<<g1, 256>>>(features, out);

    prep_kernel<<<(B_ * N_) / 256, 256>>>(cw, cb);

    dim3 g2(N_ / 128, N_ / 128, B_);      // (32, 32, 4)
    gemm_kernel<2><<<g2, 256>>>(features, out);

    rred_kernel<<<(B_ * N_) / 256, 256>>>();

    dim3 g3(N_ / 128, C_ / 128, B_);      // (32, 4, 4)
    gemm_kernel<3><<<g3, 256>>>(features, out);
}

// round 11
// speedup vs baseline: 1.0032x; 1.0032x over previous
#include <cuda_runtime.h>
#include <math.h>

// Problem constants
constexpr int B_  = 4;
constexpr int C_  = 512;
constexpr int IC_ = 256;
constexpr int H_  = 64;
constexpr int N_  = 4096;   // H*W
constexpr int OT_ = 1024;   // q(256) + k(256) + v(512) output channels

// Static scratch (allocation-free rule: __device__ globals)
__device__ float g_W[OT_ * C_];          // packed projection weights [1024, 512]
__device__ float g_bias[OT_];
__device__ float g_QKV[B_][OT_][N_];     // 67 MB: rows 0-255 = q, 256-511 = k, 512-1023 = v
__device__ float g_sqQ[B_][N_];
__device__ float g_sqK[B_][N_];
__device__ float g_Rpart[B_][N_][32];    // deterministic partial row sums of E
__device__ float g_invR[B_][N_];
__device__ float g_E[B_][N_][N_];        // 268 MB: exp(-D)

// ---------------------------------------------------------------------------
// Pack qw/kw/vw into one [1024, 512] weight matrix + bias vector
// ---------------------------------------------------------------------------
__global__ void pack_kernel(const float* __restrict__ qw, const float* __restrict__ qb,
                            const float* __restrict__ kw, const float* __restrict__ kb,
                            const float* __restrict__ vw, const float* __restrict__ vb) {
    int idx = blockIdx.x * 256 + threadIdx.x;
    if (idx < OT_ * C_) {
        int o = idx / C_, c = idx % C_;
        float v;
        if (o < IC_)          v = qw[o * C_ + c];
        else if (o < 2 * IC_) v = kw[(o - IC_) * C_ + c];
        else                  v = vw[(o - 2 * IC_) * C_ + c];
        g_W[idx] = v;
    }
    if (idx < OT_) {
        float bv;
        if (idx < IC_)          bv = qb[idx];
        else if (idx < 2 * IC_) bv = kb[idx - IC_];
        else                    bv = vb[idx - 2 * IC_];
        g_bias[idx] = bv;
    }
}

// ---------------------------------------------------------------------------
// Generic 128x128x16 tiled GEMM, 256 threads, 8x8 microtile.
// MODE 1: QKV = relu(W @ F + bias)             A=g_W [M,K] rm, B=features [K,N]
// MODE 2: E = exp(2*(Q^T K) - sqQ - sqK), Rpart A=Q [K,M] km, B=K [K,N]
// MODE 3: out = (V*invR) @ E + features        A=V [M,K] rm (scaled), B=E [K,N]
// ---------------------------------------------------------------------------
template <int MODE>
__global__ __launch_bounds__(256)
void gemm_kernel(const float* __restrict__ feat, float* __restrict__ outp) {
    constexpr int BM = 128, BN = 128, BK = 16;
    constexpr int KT  = (MODE == 1) ? C_ : (MODE == 2 ? IC_ : N_);
    constexpr int LDA = (MODE == 1) ? C_ : N_;

    __shared__ float As[BK][BM + 4];
    __shared__ float Bs[BK][BN + 4];

    const int b  = blockIdx.z;
    const int m0 = blockIdx.y * BM;
    const int n0 = blockIdx.x * BN;
    const int tid = threadIdx.x;
    const int tx = tid & 15;      // 0..15 -> output cols
    const int ty = tid >> 4;      // 0..15 -> output rows

    const float* Ap;
    const float* Bp;
    if constexpr (MODE == 1) {
        Ap = g_W;
        Bp = feat + (long)b * C_ * N_;
    } else if constexpr (MODE == 2) {
        Ap = &g_QKV[b][0][0];          // Q, [IC, N] (K-major)
        Bp = &g_QKV[b][IC_][0];        // K, [IC, N]
    } else {
        Ap = &g_QKV[b][2 * IC_][0];    // V, [C, N] row-major
        Bp = &g_E[b][0][0];            // E, [N, N]
    }

    float acc[8][8];
#pragma unroll
    for (int i = 0; i < 8; i++)
#pragma unroll
        for (int j = 0; j < 8; j++) acc[i][j] = 0.f;

    for (int k0 = 0; k0 < KT; k0 += BK) {
        // ---- load A tile ----
        if constexpr (MODE == 2) {
            // A stored [K, Mtot]: rows k, coalesced along m. No transpose needed.
#pragma unroll
            for (int i = 0; i < 2; i++) {
                int id = tid + i * 256;          // 0..511 float4s
                int kk = id >> 5;                // 0..15
                int mc = id & 31;                // 0..31
                float4 v = *(const float4*)&Ap[(long)(k0 + kk) * N_ + m0 + mc * 4];
                *(float4*)&As[kk][mc * 4] = v;
            }
        } else {
            // A row-major [Mtot, K]: load along k, transpose into As[k][m]
#pragma unroll
            for (int i = 0; i < 2; i++) {
                int id  = tid + i * 256;
                int row = id >> 2;               // 0..127
                int kc  = id & 3;                // 0..3 (float4 within k-tile)
                float4 v = *(const float4*)&Ap[(long)(m0 + row) * LDA + k0 + kc * 4];
                if constexpr (MODE == 3) {
                    float4 iv = *(const float4*)&g_invR[b][k0 + kc * 4];
                    v.x *= iv.x; v.y *= iv.y; v.z *= iv.z; v.w *= iv.w;
                }
                As[kc * 4 + 0][row] = v.x;
                As[kc * 4 + 1][row] = v.y;
                As[kc * 4 + 2][row] = v.z;
                As[kc * 4 + 3][row] = v.w;
            }
        }
        // ---- load B tile [K, N] ----
#pragma unroll
        for (int i = 0; i < 2; i++) {
            int id = tid + i * 256;
            int kk = id >> 5;
            int nc = id & 31;
            float4 v = *(const float4*)&Bp[(long)(k0 + kk) * N_ + n0 + nc * 4];
            *(float4*)&Bs[kk][nc * 4] = v;
        }
        __syncthreads();

#pragma unroll
        for (int kk = 0; kk < BK; kk++) {
            float a[8], bv[8];
            *(float4*)&a[0]  = *(const float4*)&As[kk][ty * 4];
            *(float4*)&a[4]  = *(const float4*)&As[kk][64 + ty * 4];
            *(float4*)&bv[0] = *(const float4*)&Bs[kk][tx * 4];
            *(float4*)&bv[4] = *(const float4*)&Bs[kk][64 + tx * 4];
#pragma unroll
            for (int i = 0; i < 8; i++)
#pragma unroll
                for (int j = 0; j < 8; j++) acc[i][j] += a[i] * bv[j];
        }
        __syncthreads();
    }

    // ---- epilogues ----
    const int c0 = n0 + tx * 4;
    const int c1 = c0 + 64;

    if constexpr (MODE == 1) {
#pragma unroll
        for (int i = 0; i < 8; i++) {
            int row = m0 + ((i < 4) ? (ty * 4 + i) : (64 + ty * 4 + i - 4));
            float bias = g_bias[row];
            float4 r0, r1;
            r0.x = fmaxf(acc[i][0] + bias, 0.f);
            r0.y = fmaxf(acc[i][1] + bias, 0.f);
            r0.z = fmaxf(acc[i][2] + bias, 0.f);
            r0.w = fmaxf(acc[i][3] + bias, 0.f);
            r1.x = fmaxf(acc[i][4] + bias, 0.f);
            r1.y = fmaxf(acc[i][5] + bias, 0.f);
            r1.z = fmaxf(acc[i][6] + bias, 0.f);
            r1.w = fmaxf(acc[i][7] + bias, 0.f);
            *(float4*)&g_QKV[b][row][c0] = r0;
            *(float4*)&g_QKV[b][row][c1] = r1;
        }
    } else if constexpr (MODE == 2) {
        float4 sk0 = *(const float4*)&g_sqK[b][c0];
        float4 sk1 = *(const float4*)&g_sqK[b][c1];
#pragma unroll
        for (int i = 0; i < 8; i++) {
            int row = m0 + ((i < 4) ? (ty * 4 + i) : (64 + ty * 4 + i - 4));
            float sq = g_sqQ[b][row];
            float4 e0, e1;
            e0.x = __expf(2.f * acc[i][0] - sq - sk0.x);
            e0.y = __expf(2.f * acc[i][1] - sq - sk0.y);
            e0.z = __expf(2.f * acc[i][2] - sq - sk0.z);
            e0.w = __expf(2.f * acc[i][3] - sq - sk0.w);
            e1.x = __expf(2.f * acc[i][4] - sq - sk1.x);
            e1.y = __expf(2.f * acc[i][5] - sq - sk1.y);
            e1.z = __expf(2.f * acc[i][6] - sq - sk1.z);
            e1.w = __expf(2.f * acc[i][7] - sq - sk1.w);
            *(float4*)&g_E[b][row][c0] = e0;
            *(float4*)&g_E[b][row][c1] = e1;
            // deterministic partial row sum over this block's 128 columns:
            // per-thread 8 cols, then fixed-order shfl tree across 16 tx lanes
            float s = e0.x + e0.y + e0.z + e0.w + e1.x + e1.y + e1.z + e1.w;
            s += __shfl_xor_sync(0xffffffffu, s, 1);
            s += __shfl_xor_sync(0xffffffffu, s, 2);
            s += __shfl_xor_sync(0xffffffffu, s, 4);
            s += __shfl_xor_sync(0xffffffffu, s, 8);
            if (tx == 0) g_Rpart[b][row][blockIdx.x] = s;
        }
    } else {
        const float* fbase = feat + (long)b * C_ * N_;
        float* obase = outp + (long)b * C_ * N_;
#pragma unroll
        for (int i = 0; i < 8; i++) {
            int row = m0 + ((i < 4) ? (ty * 4 + i) : (64 + ty * 4 + i - 4));
            float4 f0 = *(const float4*)&fbase[(long)row * N_ + c0];
            float4 f1 = *(const float4*)&fbase[(long)row * N_ + c1];
            float4 r0, r1;
            r0.x = acc[i][0] + f0.x; r0.y = acc[i][1] + f0.y;
            r0.z = acc[i][2] + f0.z; r0.w = acc[i][3] + f0.w;
            r1.x = acc[i][4] + f1.x; r1.y = acc[i][5] + f1.y;
            r1.z = acc[i][6] + f1.z; r1.w = acc[i][7] + f1.w;
            *(float4*)&obase[(long)row * N_ + c0] = r0;
            *(float4*)&obase[(long)row * N_ + c1] = r1;
        }
    }
}

// ---------------------------------------------------------------------------
// Add coordinate-conv cc to q and k, compute squared norms
// ---------------------------------------------------------------------------
__global__ void prep_kernel(const float* __restrict__ cw, const float* __restrict__ cb) {
    int idx = blockIdx.x * 256 + threadIdx.x;   // b*N + n
    int b = idx >> 12;
    int n = idx & (N_ - 1);
    int i = n >> 6, j = n & 63;
    float x = -1.f + 2.f * j / 63.f;   // channel 0 varies along w
    float y = -1.f + 2.f * i / 63.f;   // channel 1 varies along h
    float sq_q = 0.f, sq_k = 0.f;
    for (int ic = 0; ic < IC_; ic++) {
        float cc = fmaxf(cw[2 * ic] * x + cw[2 * ic + 1] * y + cb[ic], 0.f);
        float q = g_QKV[b][ic][n] + cc;
        float k = g_QKV[b][IC_ + ic][n] + cc;
        g_QKV[b][ic][n] = q;
        g_QKV[b][IC_ + ic][n] = k;
        sq_q += q * q;
        sq_k += k * k;
    }
    g_sqQ[b][n] = sq_q;
    g_sqK[b][n] = sq_k;
}

// ---------------------------------------------------------------------------
// Reduce the 32 deterministic partials -> invR = 1/(rowsum + 1e-14)
// ---------------------------------------------------------------------------
__global__ void rred_kernel() {
    int idx = blockIdx.x * 256 + threadIdx.x;   // b*N + n
    int b = idx >> 12;
    int n = idx & (N_ - 1);
    float s = 0.f;
#pragma unroll
    for (int p = 0; p < 32; p++) s += g_Rpart[b][n][p];
    g_invR[b][n] = 1.f / (s + 1e-14f);
}

// ---------------------------------------------------------------------------
extern "C" void kernel_launch(void* const* d_in, const int* in_sizes, int n_in,
                              void* d_out, int out_size) {
    const float* features = (const float*)d_in[0];
    const float* qw = (const float*)d_in[1];
    const float* qb = (const float*)d_in[2];
    const float* kw = (const float*)d_in[3];
    const float* kb = (const float*)d_in[4];
    const float* vw = (const float*)d_in[5];
    const float* vb = (const float*)d_in[6];
    const float* cw = (const float*)d_in[7];
    const float* cb = (const float*)d_in[8];
    float* out = (float*)d_out;

    pack_kernel<<<(OT_ * C_ + 255) / 256, 256>>>(qw, qb, kw, kb, vw, vb);

    dim3 g1(N_ / 128, OT_ / 128, B_);     // (32, 8, 4)
    gemm_kernel<1><<<g1, 256>>>(features, out);

    prep_kernel<<<(B_ * N_) / 256, 256>>>(cw, cb);

    dim3 g2(N_ / 128, N_ / 128, B_);      // (32, 32, 4)
    gemm_kernel<2><<<g2, 256>>>(features, out);

    rred_kernel<<<(B_ * N_) / 256, 256>>>();

    dim3 g3(N_ / 128, C_ / 128, B_);      // (32, 4, 4)
    gemm_kernel<3><<<g3, 256>>>(features, out);
}